// round 1
// baseline (speedup 1.0000x reference)
#include <cuda_runtime.h>
#include <cuda_bf16.h>

// Problem constants
#define BATCH 2048
#define CH    66
#define TLEN  96
#define FIN   7128      // 9 * 66 * 12
#define H1    1936
#define NCLS  14

// ---------------- scratch (static device globals; no allocs allowed) -------
__device__ float g_xt[BATCH * CH * TLEN];      // (B*C, 96)  transposed input
__device__ float g_feat[BATCH * FIN];          // (B, 7128)  concat features
__device__ float g_h[BATCH * H1];              // (B, 1936)  fc1 output

// ---------------- 1) transpose (B,T,C) -> (B*C, T) -------------------------
__global__ void transpose_kernel(const float* __restrict__ x) {
    __shared__ float sm[TLEN * CH];            // [t*66 + c]
    int b = blockIdx.x;
    const float* xb = x + (size_t)b * TLEN * CH;
    for (int i = threadIdx.x; i < TLEN * CH; i += blockDim.x) sm[i] = xb[i];
    __syncthreads();
    float* outb = g_xt + (size_t)b * CH * TLEN;
    for (int j = threadIdx.x; j < CH * TLEN; j += blockDim.x) {
        int c = j / TLEN, t = j % TLEN;
        outb[j] = sm[t * CH + c];
    }
}

// ---------------- 2) fused conv pyramid, one warp per (b,c) ----------------
// per-warp smem layout (floats):
//  [0,96)    x
//  [96,480)  buf1 : 8 x 48
//  [480,576) buf2 : 4 x 24
//  [576,632) swv  : shared conv weights (<= 8*7)
//  [632,856) wi1  : grouped conv1 weights (<= 4*8*7)
//  [856,968) wi2  : grouped conv2 weights (<= 4*4*7)
#define WBUF 968

template <int K, int PAD>
__device__ __forceinline__ void do_branch(
    const float* sx, float* buf1, float* buf2,
    float* swv, float* wi1, float* wi2,
    const float* __restrict__ w_s,  const float* __restrict__ b_s,
    const float* __restrict__ w_i1, const float* __restrict__ b_i1,
    const float* __restrict__ w_i2, const float* __restrict__ b_i2,
    int c, float* featOut, int rowbase, int lane)
{
    // stage weights for this channel into smem
    for (int i = lane; i < 8 * K; i += 32)  swv[i] = w_s[i];
    for (int i = lane; i < 32 * K; i += 32) wi1[i] = w_i1[(size_t)c * 32 * K + i];
    for (int i = lane; i < 16 * K; i += 32) wi2[i] = w_i2[(size_t)c * 16 * K + i];
    __syncwarp();

    // ---- stage 1: shared conv 1->8 (len 96), relu, pool2 -> buf1 (8 x 48)
    for (int idx = lane; idx < 8 * 48; idx += 32) {
        int o = idx / 48, p = idx % 48;
        float bo = b_s[o];
        float acc = 0.f;
#pragma unroll
        for (int dt = 0; dt < 2; ++dt) {
            int t = 2 * p + dt;
            float v = bo;
#pragma unroll
            for (int k = 0; k < K; ++k) {
                int tt = t + k - PAD;
                if (tt >= 0 && tt < TLEN) v += swv[o * K + k] * sx[tt];
            }
            acc += fmaxf(v, 0.f);
        }
        buf1[o * 48 + p] = 0.5f * acc;
    }
    __syncwarp();

    // ---- stage 2: grouped conv 8->4 (len 48), relu, pool2 -> buf2 (4 x 24)
    for (int idx = lane; idx < 4 * 24; idx += 32) {
        int j = idx / 24, p = idx % 24;
        float bj = b_i1[c * 4 + j];
        float acc = 0.f;
#pragma unroll
        for (int dt = 0; dt < 2; ++dt) {
            int t = 2 * p + dt;
            float v = bj;
#pragma unroll
            for (int i = 0; i < 8; ++i)
#pragma unroll
                for (int k = 0; k < K; ++k) {
                    int tt = t + k - PAD;
                    if (tt >= 0 && tt < 48) v += wi1[(j * 8 + i) * K + k] * buf1[i * 48 + tt];
                }
            acc += fmaxf(v, 0.f);
        }
        buf2[j * 24 + p] = 0.5f * acc;
    }
    __syncwarp();

    // ---- stage 3: grouped conv 4->4 (len 24), relu, pool2 -> feat rows
    for (int idx = lane; idx < 4 * 12; idx += 32) {
        int j = idx / 12, p = idx % 12;
        float bj = b_i2[c * 4 + j];
        float acc = 0.f;
#pragma unroll
        for (int dt = 0; dt < 2; ++dt) {
            int t = 2 * p + dt;
            float v = bj;
#pragma unroll
            for (int i = 0; i < 4; ++i)
#pragma unroll
                for (int k = 0; k < K; ++k) {
                    int tt = t + k - PAD;
                    if (tt >= 0 && tt < 24) v += wi2[(j * 4 + i) * K + k] * buf2[i * 24 + tt];
                }
            acc += fmaxf(v, 0.f);
        }
        featOut[(rowbase + j) * 12 + p] = 0.5f * acc;
    }
    __syncwarp();
}

__global__ void conv_kernel(
    const float* __restrict__ w_hs, const float* __restrict__ b_hs,
    const float* __restrict__ w_ls, const float* __restrict__ b_ls,
    const float* __restrict__ w_hi1, const float* __restrict__ b_hi1,
    const float* __restrict__ w_hi2, const float* __restrict__ b_hi2,
    const float* __restrict__ w_li1, const float* __restrict__ b_li1,
    const float* __restrict__ w_li2, const float* __restrict__ b_li2)
{
    __shared__ float smem[4 * WBUF];
    int warp = threadIdx.x >> 5, lane = threadIdx.x & 31;
    int task = blockIdx.x * 4 + warp;          // grid sized exactly: 33792*4
    int b = task / CH, c = task % CH;

    float* wb   = smem + warp * WBUF;
    float* sx   = wb;
    float* buf1 = wb + 96;
    float* buf2 = wb + 480;
    float* swv  = wb + 576;
    float* wi1  = wb + 632;
    float* wi2  = wb + 856;

    const float* xin = g_xt + (size_t)task * TLEN;
    for (int i = lane; i < TLEN; i += 32) sx[i] = xin[i];
    __syncwarp();

    float* featOut = g_feat + (size_t)b * FIN + c * 108;

    // row 0: orig = avg-pool-8
    if (lane < 12) {
        float s = 0.f;
#pragma unroll
        for (int i = 0; i < 8; ++i) s += sx[lane * 8 + i];
        featOut[lane] = s * 0.125f;
    }
    __syncwarp();

    // rows 1..4: low branch (K=3, pad=1); rows 5..8: high branch (K=7, pad=3)
    do_branch<3, 1>(sx, buf1, buf2, swv, wi1, wi2,
                    w_ls, b_ls, w_li1, b_li1, w_li2, b_li2,
                    c, featOut, 1, lane);
    do_branch<7, 3>(sx, buf1, buf2, swv, wi1, wi2,
                    w_hs, b_hs, w_hi1, b_hi1, w_hi2, b_hi2,
                    c, featOut, 5, lane);
}

// ---------------- 3) FC1: g_h = relu(g_feat @ Wf^T + bf) -------------------
// A (2048 x 7128) row-major, B (1936 x 7128) row-major  => C = A * B^T
__global__ void __launch_bounds__(256, 2) fc1_kernel(
    const float* __restrict__ Wf, const float* __restrict__ bf)
{
    const int BK = 8;
    __shared__ float As[BK][128];
    __shared__ float Bs[BK][128];

    int tid = threadIdx.x;
    int tx = tid & 15, ty = tid >> 4;
    int m0 = blockIdx.x * 128;
    int n0 = blockIdx.y * 128;

    float acc[8][8];
#pragma unroll
    for (int i = 0; i < 8; ++i)
#pragma unroll
        for (int j = 0; j < 8; ++j) acc[i][j] = 0.f;

    int lrow  = tid >> 1;          // 0..127
    int lcol4 = (tid & 1) * 4;     // 0 or 4
    const float* Aptr = g_feat + (size_t)(m0 + lrow) * FIN + lcol4;
    int brow = n0 + lrow;
    const float* Bptr = Wf + (size_t)brow * FIN + lcol4;
    bool bvalid = (brow < H1);

    for (int k0 = 0; k0 < FIN; k0 += BK) {
        float4 av = *(const float4*)(Aptr + k0);
        As[lcol4 + 0][lrow] = av.x; As[lcol4 + 1][lrow] = av.y;
        As[lcol4 + 2][lrow] = av.z; As[lcol4 + 3][lrow] = av.w;
        float4 bv = make_float4(0.f, 0.f, 0.f, 0.f);
        if (bvalid) bv = *(const float4*)(Bptr + k0);
        Bs[lcol4 + 0][lrow] = bv.x; Bs[lcol4 + 1][lrow] = bv.y;
        Bs[lcol4 + 2][lrow] = bv.z; Bs[lcol4 + 3][lrow] = bv.w;
        __syncthreads();

#pragma unroll
        for (int k = 0; k < BK; ++k) {
            float a[8], b[8];
#pragma unroll
            for (int i = 0; i < 8; ++i) a[i] = As[k][ty * 8 + i];
#pragma unroll
            for (int j = 0; j < 8; ++j) b[j] = Bs[k][tx * 8 + j];
#pragma unroll
            for (int i = 0; i < 8; ++i)
#pragma unroll
                for (int j = 0; j < 8; ++j) acc[i][j] = fmaf(a[i], b[j], acc[i][j]);
        }
        __syncthreads();
    }

#pragma unroll
    for (int i = 0; i < 8; ++i) {
        int m = m0 + ty * 8 + i;
#pragma unroll
        for (int j = 0; j < 8; ++j) {
            int n = n0 + tx * 8 + j;
            if (n < H1) g_h[(size_t)m * H1 + n] = fmaxf(acc[i][j] + bf[n], 0.f);
        }
    }
}

// ---------------- 4) FC2: out = g_h @ W2^T + b2 ----------------------------
__global__ void fc2_kernel(const float* __restrict__ W2,
                           const float* __restrict__ b2,
                           float* __restrict__ out)
{
    int m = blockIdx.x;
    int tid = threadIdx.x;           // 128 threads
    float acc[NCLS];
#pragma unroll
    for (int n = 0; n < NCLS; ++n) acc[n] = 0.f;

    const float* hrow = g_h + (size_t)m * H1;
    for (int k = tid; k < H1; k += 128) {
        float hv = hrow[k];
#pragma unroll
        for (int n = 0; n < NCLS; ++n) acc[n] += hv * W2[n * H1 + k];
    }
#pragma unroll
    for (int off = 16; off > 0; off >>= 1)
#pragma unroll
        for (int n = 0; n < NCLS; ++n)
            acc[n] += __shfl_down_sync(0xffffffffu, acc[n], off);

    __shared__ float red[4][NCLS];
    int w = tid >> 5, l = tid & 31;
    if (l == 0)
#pragma unroll
        for (int n = 0; n < NCLS; ++n) red[w][n] = acc[n];
    __syncthreads();
    if (tid < NCLS) {
        float s = red[0][tid] + red[1][tid] + red[2][tid] + red[3][tid];
        out[(size_t)m * NCLS + tid] = s + b2[tid];
    }
}

// ---------------- launch ---------------------------------------------------
extern "C" void kernel_launch(void* const* d_in, const int* in_sizes, int n_in,
                              void* d_out, int out_size)
{
    const float* x     = (const float*)d_in[0];
    const float* w_hs  = (const float*)d_in[1];
    const float* b_hs  = (const float*)d_in[2];
    const float* w_ls  = (const float*)d_in[3];
    const float* b_ls  = (const float*)d_in[4];
    const float* w_hi1 = (const float*)d_in[5];
    const float* b_hi1 = (const float*)d_in[6];
    const float* w_hi2 = (const float*)d_in[7];
    const float* b_hi2 = (const float*)d_in[8];
    const float* w_li1 = (const float*)d_in[9];
    const float* b_li1 = (const float*)d_in[10];
    const float* w_li2 = (const float*)d_in[11];
    const float* b_li2 = (const float*)d_in[12];
    const float* w_fc1 = (const float*)d_in[13];
    const float* b_fc1 = (const float*)d_in[14];
    const float* w_fc2 = (const float*)d_in[15];
    const float* b_fc2 = (const float*)d_in[16];
    float* out = (float*)d_out;

    transpose_kernel<<<BATCH, 256>>>(x);
    conv_kernel<<<(BATCH * CH) / 4, 128>>>(w_hs, b_hs, w_ls, b_ls,
                                           w_hi1, b_hi1, w_hi2, b_hi2,
                                           w_li1, b_li1, w_li2, b_li2);
    dim3 g1(BATCH / 128, (H1 + 127) / 128);   // 16 x 16
    fc1_kernel<<<g1, 256>>>(w_fc1, b_fc1);
    fc2_kernel<<<BATCH, 128>>>(w_fc2, b_fc2, out);
}

// round 7
// speedup vs baseline: 1.8743x; 1.8743x over previous
#include <cuda_runtime.h>
#include <cuda_bf16.h>
#include <cstdint>

// Problem constants
#define BATCH 2048
#define CH    66
#define TLEN  96
#define FIN   7128      // 9 * 66 * 12
#define H1    1936
#define NCLS  14

// Split-precision augmented GEMM constants
#define KSEG   7168                 // FIN padded to multiple of 64
#define KAUG   (3 * KSEG)           // 21504 : [A_hi|A_hi|A_lo] x [B_hi|B_lo|B_hi]
#define KC     64                   // K per smem chunk (64 bf16 = 128B row)
#define NCHUNK (KAUG / KC)          // 336
#define NPAD   2048                 // H1 padded

// ---------------- scratch (static device globals; no allocs allowed) -------
__device__ float g_xt[BATCH * CH * TLEN];
__device__ float g_feat[BATCH * FIN];
__device__ float g_h[BATCH * H1];
__device__ __nv_bfloat16 g_A[(size_t)BATCH * KAUG];   // 88 MB
__device__ __nv_bfloat16 g_B[(size_t)NPAD * KAUG];    // 88 MB

// ======================= PTX helpers (baseline features only) ==============
__device__ __forceinline__ uint32_t smem_u32(const void* p) {
    uint32_t a;
    asm("{ .reg .u64 t; cvta.to.shared.u64 t, %1; cvt.u32.u64 %0, t; }"
        : "=r"(a) : "l"(p));
    return a;
}
#define SWZ128(off) ((off) ^ (((off) >> 3) & 0x70))

__device__ __forceinline__ void cp_async16(uint32_t dst, const void* src) {
    asm volatile("cp.async.cg.shared.global [%0], [%1], 16;" :: "r"(dst), "l"(src));
}
#define CP_COMMIT() asm volatile("cp.async.commit_group;" ::: "memory")
#define CP_WAIT2()  asm volatile("cp.async.wait_group 2;" ::: "memory")
#define CP_WAIT0()  asm volatile("cp.async.wait_group 0;" ::: "memory")

__device__ __forceinline__ void ldsm_x4(uint32_t* r, uint32_t addr) {
    asm volatile("ldmatrix.sync.aligned.m8n8.x4.shared.b16 {%0,%1,%2,%3}, [%4];"
        : "=r"(r[0]), "=r"(r[1]), "=r"(r[2]), "=r"(r[3]) : "r"(addr));
}
__device__ __forceinline__ void mma_bf16(float* d, const uint32_t* a, const uint32_t* b) {
    asm volatile("mma.sync.aligned.m16n8k16.row.col.f32.bf16.bf16.f32 "
        "{%0,%1,%2,%3}, {%4,%5,%6,%7}, {%8,%9}, {%0,%1,%2,%3};"
        : "+f"(d[0]), "+f"(d[1]), "+f"(d[2]), "+f"(d[3])
        : "r"(a[0]), "r"(a[1]), "r"(a[2]), "r"(a[3]), "r"(b[0]), "r"(b[1]));
}

// ---------------- 1) transpose (B,T,C) -> (B*C, T) -------------------------
__global__ void transpose_kernel(const float* __restrict__ x) {
    __shared__ float sm[TLEN * CH];
    int b = blockIdx.x;
    const float* xb = x + (size_t)b * TLEN * CH;
    for (int i = threadIdx.x; i < TLEN * CH; i += blockDim.x) sm[i] = xb[i];
    __syncthreads();
    float* outb = g_xt + (size_t)b * CH * TLEN;
    for (int j = threadIdx.x; j < CH * TLEN; j += blockDim.x) {
        int c = j / TLEN, t = j % TLEN;
        outb[j] = sm[t * CH + c];
    }
}

// ---------------- 2) fused conv pyramid, one warp per (b,c) ----------------
#define WBUF 968

template <int K, int PAD>
__device__ __forceinline__ void do_branch(
    const float* sx, float* buf1, float* buf2,
    float* swv, float* wi1, float* wi2,
    const float* __restrict__ w_s,  const float* __restrict__ b_s,
    const float* __restrict__ w_i1, const float* __restrict__ b_i1,
    const float* __restrict__ w_i2, const float* __restrict__ b_i2,
    int c, float* featOut, int rowbase, int lane)
{
    for (int i = lane; i < 8 * K; i += 32)  swv[i] = w_s[i];
    for (int i = lane; i < 32 * K; i += 32) wi1[i] = w_i1[(size_t)c * 32 * K + i];
    for (int i = lane; i < 16 * K; i += 32) wi2[i] = w_i2[(size_t)c * 16 * K + i];
    __syncwarp();

    for (int idx = lane; idx < 8 * 48; idx += 32) {
        int o = idx / 48, p = idx % 48;
        float bo = b_s[o];
        float acc = 0.f;
#pragma unroll
        for (int dt = 0; dt < 2; ++dt) {
            int t = 2 * p + dt;
            float v = bo;
#pragma unroll
            for (int k = 0; k < K; ++k) {
                int tt = t + k - PAD;
                if (tt >= 0 && tt < TLEN) v += swv[o * K + k] * sx[tt];
            }
            acc += fmaxf(v, 0.f);
        }
        buf1[o * 48 + p] = 0.5f * acc;
    }
    __syncwarp();

    for (int idx = lane; idx < 4 * 24; idx += 32) {
        int j = idx / 24, p = idx % 24;
        float bj = b_i1[c * 4 + j];
        float acc = 0.f;
#pragma unroll
        for (int dt = 0; dt < 2; ++dt) {
            int t = 2 * p + dt;
            float v = bj;
#pragma unroll
            for (int i = 0; i < 8; ++i)
#pragma unroll
                for (int k = 0; k < K; ++k) {
                    int tt = t + k - PAD;
                    if (tt >= 0 && tt < 48) v += wi1[(j * 8 + i) * K + k] * buf1[i * 48 + tt];
                }
            acc += fmaxf(v, 0.f);
        }
        buf2[j * 24 + p] = 0.5f * acc;
    }
    __syncwarp();

    for (int idx = lane; idx < 4 * 12; idx += 32) {
        int j = idx / 12, p = idx % 12;
        float bj = b_i2[c * 4 + j];
        float acc = 0.f;
#pragma unroll
        for (int dt = 0; dt < 2; ++dt) {
            int t = 2 * p + dt;
            float v = bj;
#pragma unroll
            for (int i = 0; i < 4; ++i)
#pragma unroll
                for (int k = 0; k < K; ++k) {
                    int tt = t + k - PAD;
                    if (tt >= 0 && tt < 24) v += wi2[(j * 4 + i) * K + k] * buf2[i * 24 + tt];
                }
            acc += fmaxf(v, 0.f);
        }
        featOut[(rowbase + j) * 12 + p] = 0.5f * acc;
    }
    __syncwarp();
}

__global__ void conv_kernel(
    const float* __restrict__ w_hs, const float* __restrict__ b_hs,
    const float* __restrict__ w_ls, const float* __restrict__ b_ls,
    const float* __restrict__ w_hi1, const float* __restrict__ b_hi1,
    const float* __restrict__ w_hi2, const float* __restrict__ b_hi2,
    const float* __restrict__ w_li1, const float* __restrict__ b_li1,
    const float* __restrict__ w_li2, const float* __restrict__ b_li2)
{
    __shared__ float smem[4 * WBUF];
    int warp = threadIdx.x >> 5, lane = threadIdx.x & 31;
    int task = blockIdx.x * 4 + warp;
    int b = task / CH, c = task % CH;

    float* wb   = smem + warp * WBUF;
    float* sx   = wb;
    float* buf1 = wb + 96;
    float* buf2 = wb + 480;
    float* swv  = wb + 576;
    float* wi1  = wb + 632;
    float* wi2  = wb + 856;

    const float* xin = g_xt + (size_t)task * TLEN;
    for (int i = lane; i < TLEN; i += 32) sx[i] = xin[i];
    __syncwarp();

    float* featOut = g_feat + (size_t)b * FIN + c * 108;

    if (lane < 12) {
        float s = 0.f;
#pragma unroll
        for (int i = 0; i < 8; ++i) s += sx[lane * 8 + i];
        featOut[lane] = s * 0.125f;
    }
    __syncwarp();

    do_branch<3, 1>(sx, buf1, buf2, swv, wi1, wi2,
                    w_ls, b_ls, w_li1, b_li1, w_li2, b_li2,
                    c, featOut, 1, lane);
    do_branch<7, 3>(sx, buf1, buf2, swv, wi1, wi2,
                    w_hs, b_hs, w_hi1, b_hi1, w_hi2, b_hi2,
                    c, featOut, 5, lane);
}

// ---------------- 2b) hi/lo split conversion -------------------------------
__global__ void convertA_kernel() {
    int i = blockIdx.x * blockDim.x + threadIdx.x;      // over 2048 * 1792
    int m = i / (KSEG / 4);
    int k = (i % (KSEG / 4)) * 4;
    float4 v = make_float4(0.f, 0.f, 0.f, 0.f);
    if (k < FIN) v = *(const float4*)(g_feat + (size_t)m * FIN + k);
    union { __nv_bfloat16 b[4]; uint2 u; } H, L;
    const float vv[4] = {v.x, v.y, v.z, v.w};
#pragma unroll
    for (int j = 0; j < 4; ++j) {
        __nv_bfloat16 h = __float2bfloat16(vv[j]);
        H.b[j] = h;
        L.b[j] = __float2bfloat16(vv[j] - __bfloat162float(h));
    }
    __nv_bfloat16* row = g_A + (size_t)m * KAUG;
    *(uint2*)(row + 0 * KSEG + k) = H.u;
    *(uint2*)(row + 1 * KSEG + k) = H.u;
    *(uint2*)(row + 2 * KSEG + k) = L.u;
}

__global__ void convertB_kernel(const float* __restrict__ W) {
    int i = blockIdx.x * blockDim.x + threadIdx.x;      // over 2048 * 1792
    int n = i / (KSEG / 4);
    int k = (i % (KSEG / 4)) * 4;
    float4 v = make_float4(0.f, 0.f, 0.f, 0.f);
    if (n < H1 && k < FIN) v = *(const float4*)(W + (size_t)n * FIN + k);
    union { __nv_bfloat16 b[4]; uint2 u; } H, L;
    const float vv[4] = {v.x, v.y, v.z, v.w};
#pragma unroll
    for (int j = 0; j < 4; ++j) {
        __nv_bfloat16 h = __float2bfloat16(vv[j]);
        H.b[j] = h;
        L.b[j] = __float2bfloat16(vv[j] - __bfloat162float(h));
    }
    __nv_bfloat16* row = g_B + (size_t)n * KAUG;
    *(uint2*)(row + 0 * KSEG + k) = H.u;
    *(uint2*)(row + 1 * KSEG + k) = L.u;
    *(uint2*)(row + 2 * KSEG + k) = H.u;
}

// ---------------- 3) FC1 via mma.sync bf16: g_h = relu(A' @ B'^T + bf) -----
// CTA tile 128(M) x 256(N), 8 warps of 64x64, K pipelined in 64-elem chunks.
#define STAGES      4
#define SM_A_BYTES  (128 * 128)                 // 16 KB
#define SM_B_BYTES  (256 * 128)                 // 32 KB
#define STAGE_BYTES (SM_A_BYTES + SM_B_BYTES)   // 48 KB
#define SMEM_GEMM   (STAGES * STAGE_BYTES)      // 192 KB

__global__ void __launch_bounds__(256, 1) fc1_mma_kernel(const float* __restrict__ bf)
{
    extern __shared__ char smem[];
    const uint32_t smb = smem_u32(smem);
    const int tid = threadIdx.x, wid = tid >> 5, lane = tid & 31;
    const int m0 = blockIdx.x * 128;
    const int n0 = blockIdx.y * 256;
    const int wm = wid & 1;            // warp row: 0..1   (64 M-rows each)
    const int wn = wid >> 1;           // warp col: 0..3   (64 N-cols each)

    const char* Ag = (const char*)g_A + (size_t)m0 * (KAUG * 2);
    const char* Bg = (const char*)g_B + (size_t)n0 * (KAUG * 2);

    // cp.async geometry: 16B chunks, 8 per 128B row
    const int ra[4] = { tid >> 3, (tid + 256) >> 3, (tid + 512) >> 3, (tid + 768) >> 3 };
    const int ca = (tid & 7) * 16;

    auto load_chunk = [&](int chunk, int stage) {
        const size_t koff = (size_t)chunk * (KC * 2);
        const uint32_t sA = smb + stage * STAGE_BYTES;
        const uint32_t sB = sA + SM_A_BYTES;
#pragma unroll
        for (int j = 0; j < 4; ++j) {
            int r = ra[j];
            cp_async16(sA + SWZ128(r * 128 + ca),
                       Ag + (size_t)r * (KAUG * 2) + koff + ca);
        }
#pragma unroll
        for (int j = 0; j < 8; ++j) {
            int r = (tid + 256 * j) >> 3;
            cp_async16(sB + SWZ128(r * 128 + ca),
                       Bg + (size_t)r * (KAUG * 2) + koff + ca);
        }
        CP_COMMIT();
    };

    // ldmatrix per-lane geometry (offsets within a stage, before swizzle)
    //  A frags: row = wm*64 + im*16 + (lane&15), kbyte = (lane>>4)*16
    //  B frags: n   = wn*64 + ip*16 + ((lane&7) | ((lane>>4)<<3)), kbyte = ((lane>>3)&1)*16
    const int a_row  = wm * 64 + (lane & 15);
    const int a_kb   = (lane >> 4) * 16;
    const int b_row  = wn * 64 + ((lane & 7) | ((lane >> 4) << 3));
    const int b_kb   = ((lane >> 3) & 1) * 16;

    float acc[4][8][4];
#pragma unroll
    for (int im = 0; im < 4; ++im)
#pragma unroll
        for (int in = 0; in < 8; ++in)
#pragma unroll
            for (int r = 0; r < 4; ++r) acc[im][in][r] = 0.f;

    // prologue
    load_chunk(0, 0);
    load_chunk(1, 1);
    load_chunk(2, 2);

    for (int i = 0; i < NCHUNK; ++i) {
        const int s = i & 3;
        CP_WAIT2();
        __syncthreads();
        if (i + 3 < NCHUNK) load_chunk(i + 3, (i + 3) & 3);
        else CP_COMMIT();

        const uint32_t sA = smb + s * STAGE_BYTES;
        const uint32_t sB = sA + SM_A_BYTES;
#pragma unroll
        for (int ks = 0; ks < 4; ++ks) {
            uint32_t a[4][4];
#pragma unroll
            for (int im = 0; im < 4; ++im)
                ldsm_x4(a[im], sA + SWZ128((a_row + im * 16) * 128 + a_kb + ks * 32));
            uint32_t b[4][4];                  // [pair of n-subtiles][4 regs]
#pragma unroll
            for (int ip = 0; ip < 4; ++ip)
                ldsm_x4(b[ip], sB + SWZ128((b_row + ip * 16) * 128 + b_kb + ks * 32));
#pragma unroll
            for (int im = 0; im < 4; ++im)
#pragma unroll
                for (int ip = 0; ip < 4; ++ip) {
                    mma_bf16(acc[im][2 * ip + 0], a[im], &b[ip][0]);
                    mma_bf16(acc[im][2 * ip + 1], a[im], &b[ip][2]);
                }
        }
    }
    CP_WAIT0();

    // epilogue: bias + relu, write g_h
    const int erow = m0 + wm * 64 + (lane >> 2);
    const int ecol = n0 + wn * 64 + (lane & 3) * 2;
#pragma unroll
    for (int im = 0; im < 4; ++im) {
#pragma unroll
        for (int in = 0; in < 8; ++in) {
            const int n = ecol + in * 8;
            if (n < H1) {
                const float b0 = bf[n], b1 = bf[n + 1];
                const int r0 = erow + im * 16;
                float2 v0, v1;
                v0.x = fmaxf(acc[im][in][0] + b0, 0.f);
                v0.y = fmaxf(acc[im][in][1] + b1, 0.f);
                v1.x = fmaxf(acc[im][in][2] + b0, 0.f);
                v1.y = fmaxf(acc[im][in][3] + b1, 0.f);
                *(float2*)(g_h + (size_t)r0 * H1 + n) = v0;
                *(float2*)(g_h + (size_t)(r0 + 8) * H1 + n) = v1;
            }
        }
    }
}

// ---------------- 4) FC2: out = g_h @ W2^T + b2 ----------------------------
__global__ void fc2_kernel(const float* __restrict__ W2,
                           const float* __restrict__ b2,
                           float* __restrict__ out)
{
    int m = blockIdx.x;
    int tid = threadIdx.x;
    float acc[NCLS];
#pragma unroll
    for (int n = 0; n < NCLS; ++n) acc[n] = 0.f;

    const float* hrow = g_h + (size_t)m * H1;
    for (int k = tid; k < H1; k += 128) {
        float hv = hrow[k];
#pragma unroll
        for (int n = 0; n < NCLS; ++n) acc[n] += hv * W2[n * H1 + k];
    }
#pragma unroll
    for (int off = 16; off > 0; off >>= 1)
#pragma unroll
        for (int n = 0; n < NCLS; ++n)
            acc[n] += __shfl_down_sync(0xffffffffu, acc[n], off);

    __shared__ float red[4][NCLS];
    int w = tid >> 5, l = tid & 31;
    if (l == 0)
#pragma unroll
        for (int n = 0; n < NCLS; ++n) red[w][n] = acc[n];
    __syncthreads();
    if (tid < NCLS) {
        float s = red[0][tid] + red[1][tid] + red[2][tid] + red[3][tid];
        out[(size_t)m * NCLS + tid] = s + b2[tid];
    }
}

// ---------------- launch ---------------------------------------------------
extern "C" void kernel_launch(void* const* d_in, const int* in_sizes, int n_in,
                              void* d_out, int out_size)
{
    const float* x     = (const float*)d_in[0];
    const float* w_hs  = (const float*)d_in[1];
    const float* b_hs  = (const float*)d_in[2];
    const float* w_ls  = (const float*)d_in[3];
    const float* b_ls  = (const float*)d_in[4];
    const float* w_hi1 = (const float*)d_in[5];
    const float* b_hi1 = (const float*)d_in[6];
    const float* w_hi2 = (const float*)d_in[7];
    const float* b_hi2 = (const float*)d_in[8];
    const float* w_li1 = (const float*)d_in[9];
    const float* b_li1 = (const float*)d_in[10];
    const float* w_li2 = (const float*)d_in[11];
    const float* b_li2 = (const float*)d_in[12];
    const float* w_fc1 = (const float*)d_in[13];
    const float* b_fc1 = (const float*)d_in[14];
    const float* w_fc2 = (const float*)d_in[15];
    const float* b_fc2 = (const float*)d_in[16];
    float* out = (float*)d_out;

    cudaFuncSetAttribute(fc1_mma_kernel,
                         cudaFuncAttributeMaxDynamicSharedMemorySize, SMEM_GEMM);

    transpose_kernel<<<BATCH, 256>>>(x);
    convertB_kernel<<<(NPAD * (KSEG / 4)) / 256, 256>>>(w_fc1);
    conv_kernel<<<(BATCH * CH) / 4, 128>>>(w_hs, b_hs, w_ls, b_ls,
                                           w_hi1, b_hi1, w_hi2, b_hi2,
                                           w_li1, b_li1, w_li2, b_li2);
    convertA_kernel<<<(BATCH * (KSEG / 4)) / 256, 256>>>();
    dim3 g1(BATCH / 128, NPAD / 256);   // 16 x 8
    fc1_mma_kernel<<<g1, 256, SMEM_GEMM>>>(b_fc1);
    fc2_kernel<<<BATCH, 128>>>(w_fc2, b_fc2, out);
}